// round 16
// baseline (speedup 1.0000x reference)
#include <cuda_runtime.h>
#include <cuda_fp16.h>
#include <cstdint>

#define BB 8
#define SS 2048
#define HH 16
#define DD 64
#define DM 1024
#define SC 512

__device__ __half g_kc[BB*HH*SC*DD];   // [bh][c][d]
__device__ __half g_vc[BB*HH*SC*DD];   // [bh][c][d]
__device__ __half g_ao[BB*SS*DM];      // attention out, fp16
__device__ __half g_wh[DM*DM];         // W in fp16, [k][n]

__device__ __forceinline__ unsigned pack2(float lo, float hi){
  unsigned d; asm("cvt.rn.f16x2.f32 %0, %1, %2;" : "=r"(d) : "f"(hi), "f"(lo)); return d;
}
__device__ __forceinline__ unsigned ex2h2(unsigned a){
  unsigned d; asm("ex2.approx.f16x2 %0, %1;" : "=r"(d) : "r"(a)); return d;
}
__device__ __forceinline__ void mma16(float* c, uint4 a, unsigned b0, unsigned b1){
  asm volatile(
    "mma.sync.aligned.m16n8k16.row.col.f32.f16.f16.f32 "
    "{%0,%1,%2,%3},{%4,%5,%6,%7},{%8,%9},{%0,%1,%2,%3};"
    : "+f"(c[0]), "+f"(c[1]), "+f"(c[2]), "+f"(c[3])
    : "r"(a.x), "r"(a.y), "r"(a.z), "r"(a.w), "r"(b0), "r"(b1));
}
__device__ __forceinline__ uint4 ldsm4(unsigned addr){
  uint4 r;
  asm volatile("ldmatrix.sync.aligned.m8n8.x4.shared.b16 {%0,%1,%2,%3}, [%4];"
    : "=r"(r.x), "=r"(r.y), "=r"(r.z), "=r"(r.w) : "r"(addr));
  return r;
}
__device__ __forceinline__ uint4 ldsm4t(unsigned addr){
  uint4 r;
  asm volatile("ldmatrix.sync.aligned.m8n8.x4.trans.shared.b16 {%0,%1,%2,%3}, [%4];"
    : "=r"(r.x), "=r"(r.y), "=r"(r.z), "=r"(r.w) : "r"(addr));
  return r;
}
__device__ __forceinline__ void cpa16(unsigned saddr, const void* g){
  asm volatile("cp.async.cg.shared.global [%0], [%1], 16;" :: "r"(saddr), "l"(g) : "memory");
}
#define CP_COMMIT() asm volatile("cp.async.commit_group;" ::: "memory")
#define CP_WAIT(n)  asm volatile("cp.async.wait_group %0;" :: "n"(n) : "memory")

// ============ kernel 0: W f32 -> fp16 ======================================
__global__ void __launch_bounds__(256)
convert_w(const float* __restrict__ W, __half* __restrict__ Wh)
{
  size_t i = ((size_t)blockIdx.x*256 + threadIdx.x)*8;
  float4 v0 = *reinterpret_cast<const float4*>(W+i);
  float4 v1 = *reinterpret_cast<const float4*>(W+i+4);
  uint4 u; u.x=pack2(v0.x,v0.y); u.y=pack2(v0.z,v0.w);
  u.z=pack2(v1.x,v1.y); u.w=pack2(v1.z,v1.w);
  *reinterpret_cast<uint4*>(Wh+i) = u;
}

// ============ kernel 1: K+V compression fused (gathered GEMM) =============
// grid 1024: blocks [0,512) do K, [512,1024) do V.
__global__ void __launch_bounds__(256,2)
compress_kernel(const float* __restrict__ pre_k, const float* __restrict__ kker,
                const float* __restrict__ kbias, __half* __restrict__ outk,
                const float* __restrict__ pre_v, const float* __restrict__ vker,
                const float* __restrict__ vbias, __half* __restrict__ outv)
{
  extern __shared__ char sm[];
  unsigned sbase = (unsigned)__cvta_generic_to_shared(sm);
  int sel = blockIdx.x >> 9;
  int bx  = blockIdx.x & 511;
  const float* pre  = sel ? pre_v : pre_k;
  const float* ker  = sel ? vker  : kker;
  const float* bias = sel ? vbias : kbias;
  __half* outc      = sel ? outv  : outk;

  int tid=threadIdx.x, warp=tid>>5, lane=tid&31, gid=lane>>2, tig=lane&3;
  int bh = bx>>2, t0 = (bx&3)*128;
  int b = bh>>4, h = bh&15;
  const float* base = pre + ((size_t)b*SS*HH + h)*DD;
  int wm = warp>>1, wn = warp&1;

  float acc[2][4][4];
  #pragma unroll
  for (int m=0;m<2;m++)
    #pragma unroll
    for (int j=0;j<4;j++) acc[m][j][0]=acc[m][j][1]=acc[m][j][2]=acc[m][j][3]=0.f;

  auto stage = [&](int w, int bf){
    #pragma unroll
    for (int i=0;i<4;i++){
      int idx = tid + i*256, row = idx>>3, cv = idx&7;
      const float4* g = reinterpret_cast<const float4*>(
          base + (size_t)((t0+row)*4 + w)*(HH*DD) + cv*8);
      float4 v0 = g[0], v1 = g[1];
      uint4 u; u.x=pack2(v0.x,v0.y); u.y=pack2(v0.z,v0.w);
      u.z=pack2(v1.x,v1.y); u.w=pack2(v1.z,v1.w);
      *reinterpret_cast<uint4*>(sm + bf*16384 + row*128 + ((cv ^ (row&7))<<4)) = u;
    }
    #pragma unroll
    for (int i=0;i<2;i++){
      int idx = tid + i*256, row = idx>>3, cv = idx&7;
      const float4* g = reinterpret_cast<const float4*>(
          ker + (size_t)w*DD*DD + row*DD + cv*8);
      float4 v0 = g[0], v1 = g[1];
      uint4 u; u.x=pack2(v0.x,v0.y); u.y=pack2(v0.z,v0.w);
      u.z=pack2(v1.x,v1.y); u.w=pack2(v1.z,v1.w);
      *reinterpret_cast<uint4*>(sm + 32768 + bf*8192 + row*128 + ((cv ^ (row&7))<<4)) = u;
    }
  };

  stage(0,0); __syncthreads();
  for (int w=0; w<4; w++){
    int bf = w&1;
    if (w<3) stage(w+1, bf^1);
    unsigned Ab = sbase + bf*16384;
    unsigned Bb = sbase + 32768 + bf*8192;
    #pragma unroll
    for (int k16=0;k16<4;k16++){
      uint4 aa[2];
      #pragma unroll
      for (int mt=0;mt<2;mt++){
        int row = wm*32 + mt*16 + (lane&7) + ((lane>>3)&1)*8;
        int ch = k16*2 + (lane>>4);
        aa[mt] = ldsm4(Ab + row*128 + (((unsigned)(ch ^ (row&7)))<<4));
      }
      #pragma unroll
      for (int jj=0;jj<2;jj++){
        int row = k16*16 + (lane&7) + ((lane>>4)<<3);
        int ch = wn*4 + jj*2 + ((lane>>3)&1);
        uint4 bb = ldsm4t(Bb + row*128 + (((unsigned)(ch ^ (row&7)))<<4));
        mma16(acc[0][2*jj],   aa[0], bb.x, bb.z);
        mma16(acc[0][2*jj+1], aa[0], bb.y, bb.w);
        mma16(acc[1][2*jj],   aa[1], bb.x, bb.z);
        mma16(acc[1][2*jj+1], aa[1], bb.y, bb.w);
      }
    }
    __syncthreads();
  }

  #pragma unroll
  for (int m=0;m<2;m++){
    int rlo = t0 + wm*32 + m*16 + gid, rhi = rlo+8;
    #pragma unroll
    for (int j=0;j<4;j++){
      int col = wn*32 + j*8 + tig*2;
      float b0 = bias[col], b1 = bias[col+1];
      *reinterpret_cast<__half2*>(outc + ((size_t)bh*SC+rlo)*DD + col) =
          __floats2half2_rn(acc[m][j][0]+b0, acc[m][j][1]+b1);
      *reinterpret_cast<__half2*>(outc + ((size_t)bh*SC+rhi)*DD + col) =
          __floats2half2_rn(acc[m][j][2]+b0, acc[m][j][3]+b1);
    }
  }
}

// ============ kernel 2: flash attention — 16q/warp, 2 CTA/SM (R15) =========
__global__ void __launch_bounds__(256,2)
attn_kernel(const float* __restrict__ preq)
{
  extern __shared__ char sm[];
  unsigned sbase = (unsigned)__cvta_generic_to_shared(sm);
  int tid=threadIdx.x, warp=tid>>5, lane=tid&31, gid=lane>>2, tig=lane&3;
  int bh = blockIdx.y, b = bh>>4, h = bh&15;
  int q0 = blockIdx.x*128, m0 = warp*16;
  const float* qb = preq + ((size_t)b*SS*HH + h)*DD;
  const __half* kb = g_kc + (size_t)bh*SC*DD;
  const __half* vb = g_vc + (size_t)bh*SC*DD;
  const float scale2 = 0.125f * 1.44269504f;

  auto stage = [&](int ch0, int bf){
    int c0 = ch0*64;
    #pragma unroll
    for (int i=0;i<2;i++){
      int idx = tid + i*256, row = idx>>3, cv = idx&7;
      unsigned sw = ((unsigned)(cv ^ (row&7)))<<4;
      cpa16(sbase + bf*8192 + row*128 + sw, kb + (size_t)(c0+row)*DD + cv*8);
      cpa16(sbase + 16384 + bf*8192 + row*128 + sw, vb + (size_t)(c0+row)*DD + cv*8);
    }
  };

  stage(0,0); CP_COMMIT();

  #pragma unroll
  for (int i=0;i<4;i++){
    int idx = tid + i*256, row = idx>>3, cv = idx&7;
    const float4* g = reinterpret_cast<const float4*>(
        qb + (size_t)(q0+row)*(HH*DD) + cv*8);
    float4 v0 = g[0], v1 = g[1];
    uint4 u;
    u.x=pack2(v0.x*scale2, v0.y*scale2); u.y=pack2(v0.z*scale2, v0.w*scale2);
    u.z=pack2(v1.x*scale2, v1.y*scale2); u.w=pack2(v1.z*scale2, v1.w*scale2);
    *reinterpret_cast<uint4*>(sm + 32768 + row*128 + ((cv ^ (row&7))<<4)) = u;
  }
  unsigned Qb = sbase + 32768;
  __syncthreads();

  uint4 qf[4];
  #pragma unroll
  for (int k16=0;k16<4;k16++){
    int row = m0 + (lane&7) + ((lane>>3)&1)*8;
    int cc = k16*2 + (lane>>4);
    qf[k16] = ldsm4(Qb + row*128 + (((unsigned)(cc ^ (row&7)))<<4));
  }

  float o[8][4];
  #pragma unroll
  for (int j=0;j<8;j++) o[j][0]=o[j][1]=o[j][2]=o[j][3]=0.f;
  float accl[4] = {0.f,0.f,0.f,0.f};
  const unsigned bone = (gid==0) ? 0x3C003C00u : 0u;

  for (int ch=0; ch<8; ch++){
    int bf = ch&1;
    CP_WAIT(0);
    __syncthreads();
    if (ch<7){ stage(ch+1, bf^1); CP_COMMIT(); }
    unsigned Kb = sbase + bf*8192;
    unsigned Vb = sbase + 16384 + bf*8192;

    float s[8][4];
    #pragma unroll
    for (int j=0;j<8;j++) s[j][0]=s[j][1]=s[j][2]=s[j][3]=0.f;
    #pragma unroll
    for (int k16=0;k16<4;k16++){
      #pragma unroll
      for (int jj=0;jj<4;jj++){
        int row = jj*16 + (lane&7) + ((lane>>3)&1)*8;
        int cc = k16*2 + (lane>>4);
        uint4 kk = ldsm4(Kb + row*128 + (((unsigned)(cc ^ (row&7)))<<4));
        mma16(s[2*jj],   qf[k16], kk.x, kk.z);
        mma16(s[2*jj+1], qf[k16], kk.y, kk.w);
      }
    }

    uint32_t pa[4][4];
    #pragma unroll
    for (int j=0;j<8;j++){
      unsigned e01 = ex2h2(pack2(s[j][0], s[j][1]));
      unsigned e23 = ex2h2(pack2(s[j][2], s[j][3]));
      int blk = j>>1;
      if ((j&1)==0){ pa[blk][0]=e01; pa[blk][1]=e23; }
      else         { pa[blk][2]=e01; pa[blk][3]=e23; }
    }

    #pragma unroll
    for (int jj=0;jj<4;jj++){
      uint4 a = make_uint4(pa[jj][0], pa[jj][1], pa[jj][2], pa[jj][3]);
      mma16(accl, a, bone, bone);
      #pragma unroll
      for (int dd=0;dd<4;dd++){
        int row = jj*16 + (lane&7) + ((lane>>4)<<3);
        int cc = dd*2 + ((lane>>3)&1);
        uint4 vv = ldsm4t(Vb + row*128 + (((unsigned)(cc ^ (row&7)))<<4));
        mma16(o[2*dd],   a, vv.x, vv.z);
        mma16(o[2*dd+1], a, vv.y, vv.w);
      }
    }
  }

  float rl = __shfl_sync(~0u, accl[0], lane & ~3);
  float rh = __shfl_sync(~0u, accl[2], lane & ~3);
  float il = 1.f/rl, ih = 1.f/rh;
  int qlo = q0+m0+gid, qhi = qlo+8;
  __half* olo = g_ao + ((size_t)(b*SS+qlo)*HH + h)*DD;
  __half* ohi = g_ao + ((size_t)(b*SS+qhi)*HH + h)*DD;
  #pragma unroll
  for (int j=0;j<8;j++){
    int col = j*8 + tig*2;
    *reinterpret_cast<__half2*>(olo + col) =
        __floats2half2_rn(o[j][0]*il, o[j][1]*il);
    *reinterpret_cast<__half2*>(ohi + col) =
        __floats2half2_rn(o[j][2]*ih, o[j][3]*ih);
  }
}

// ============ kernel 3: projection — warp 64x64, block 128x256 =============
// grid (128,4). 8 warps: wm=warp&1 (m-half), wn=warp>>1 (n-quarter).
// k-chunk 64, 3-stage cp.async. smem: A 3x16KB @0, B 3x32KB @49152 -> 147456.
__global__ void __launch_bounds__(256,1)
proj_kernel(const __half* __restrict__ Wh, float* __restrict__ out)
{
  extern __shared__ char sm[];
  unsigned sbase = (unsigned)__cvta_generic_to_shared(sm);
  int tid=threadIdx.x, warp=tid>>5, lane=tid&31, gid=lane>>2, tig=lane&3;
  int r0 = blockIdx.x*128, n0 = blockIdx.y*256;
  int wm = warp&1, wn = warp>>1;

  float acc[4][8][4];
  #pragma unroll
  for (int m=0;m<4;m++)
    #pragma unroll
    for (int j=0;j<8;j++) acc[m][j][0]=acc[m][j][1]=acc[m][j][2]=acc[m][j][3]=0.f;

  auto stage = [&](int kc, int st){
    #pragma unroll
    for (int i=0;i<4;i++){                 // A: 128 rows x 8 chunks (16KB)
      int idx = tid + i*256, row = idx>>3, cv = idx&7;
      cpa16(sbase + st*16384 + row*128 + (((unsigned)(cv ^ (row&7)))<<4),
            g_ao + (size_t)(r0+row)*DM + kc*64 + cv*8);
    }
    #pragma unroll
    for (int i=0;i<8;i++){                 // B: 64 k-rows x 32 chunks (32KB)
      int idx = tid + i*256, row = idx>>5, cv = idx&31;
      cpa16(sbase + 49152 + st*32768 + row*512 + (((unsigned)(cv ^ (row&7)))<<4),
            Wh + (size_t)(kc*64+row)*DM + n0 + cv*8);
    }
  };

  stage(0,0); CP_COMMIT();
  stage(1,1); CP_COMMIT();

  for (int kc=0; kc<16; kc++){
    int st = kc % 3;
    CP_WAIT(1);
    __syncthreads();
    if (kc+2 < 16){ stage(kc+2, (kc+2)%3); CP_COMMIT(); }
    unsigned Ab = sbase + st*16384;
    unsigned Bb = sbase + 49152 + st*32768;
    #pragma unroll
    for (int k16=0;k16<4;k16++){
      uint4 aa[4];
      #pragma unroll
      for (int mt=0;mt<4;mt++){
        int row = wm*64 + mt*16 + (lane&7) + ((lane>>3)&1)*8;
        int cc = k16*2 + (lane>>4);
        aa[mt] = ldsm4(Ab + row*128 + (((unsigned)(cc ^ (row&7)))<<4));
      }
      #pragma unroll
      for (int dd=0;dd<4;dd++){
        int row = k16*16 + (lane&7) + ((lane>>4)<<3);
        int cc = wn*8 + dd*2 + ((lane>>3)&1);
        uint4 bb = ldsm4t(Bb + row*512 + (((unsigned)(cc ^ (row&7)))<<4));
        #pragma unroll
        for (int mt=0;mt<4;mt++){
          mma16(acc[mt][2*dd],   aa[mt], bb.x, bb.z);
          mma16(acc[mt][2*dd+1], aa[mt], bb.y, bb.w);
        }
      }
    }
  }

  #pragma unroll
  for (int mt=0;mt<4;mt++){
    int rlo = r0 + wm*64 + mt*16 + gid, rhi = rlo+8;
    #pragma unroll
    for (int j=0;j<8;j++){
      int col = n0 + wn*64 + j*8 + tig*2;
      *reinterpret_cast<float2*>(out + (size_t)rlo*DM + col) = make_float2(acc[mt][j][0], acc[mt][j][1]);
      *reinterpret_cast<float2*>(out + (size_t)rhi*DM + col) = make_float2(acc[mt][j][2], acc[mt][j][3]);
    }
  }
}

extern "C" void kernel_launch(void* const* d_in, const int* in_sizes, int n_in,
                              void* d_out, int out_size)
{
  const float* pre_q = (const float*)d_in[0];
  const float* pre_k = (const float*)d_in[1];
  const float* pre_v = (const float*)d_in[2];
  const float* kker  = (const float*)d_in[3];
  const float* kbias = (const float*)d_in[4];
  const float* vker  = (const float*)d_in[5];
  const float* vbias = (const float*)d_in[6];
  const float* ow    = (const float*)d_in[7];
  float* out = (float*)d_out;

  __half *g_kc_p, *g_vc_p, *g_wh_p;
  cudaGetSymbolAddress((void**)&g_kc_p, g_kc);
  cudaGetSymbolAddress((void**)&g_vc_p, g_vc);
  cudaGetSymbolAddress((void**)&g_wh_p, g_wh);

  const int smemC = 49152;
  const int smemA = 49152;
  const int smemP = 147456;
  cudaFuncSetAttribute(compress_kernel, cudaFuncAttributeMaxDynamicSharedMemorySize, smemC);
  cudaFuncSetAttribute(attn_kernel, cudaFuncAttributeMaxDynamicSharedMemorySize, smemA);
  cudaFuncSetAttribute(proj_kernel, cudaFuncAttributeMaxDynamicSharedMemorySize, smemP);

  convert_w<<<512, 256>>>(ow, g_wh_p);
  compress_kernel<<<1024, 256, smemC>>>(pre_k, kker, kbias, g_kc_p,
                                        pre_v, vker, vbias, g_vc_p);
  attn_kernel<<<dim3(16,128), 256, smemA>>>(pre_q);
  proj_kernel<<<dim3(128,4), 256, smemP>>>(g_wh_p, out);
}

// round 17
// speedup vs baseline: 1.1099x; 1.1099x over previous
#include <cuda_runtime.h>
#include <cuda_fp16.h>
#include <cstdint>

#define BB 8
#define SS 2048
#define HH 16
#define DD 64
#define DM 1024
#define SC 512

__device__ __half g_kc[BB*HH*SC*DD];   // [bh][c][d]
__device__ __half g_vc[BB*HH*SC*DD];   // [bh][c][d]
__device__ __half g_ao[BB*SS*DM];      // attention out, fp16
__device__ __half g_wh[DM*DM];         // W in fp16, [k][n]

__device__ __forceinline__ unsigned pack2(float lo, float hi){
  unsigned d; asm("cvt.rn.f16x2.f32 %0, %1, %2;" : "=r"(d) : "f"(hi), "f"(lo)); return d;
}
__device__ __forceinline__ unsigned ex2h2(unsigned a){
  unsigned d; asm("ex2.approx.f16x2 %0, %1;" : "=r"(d) : "r"(a)); return d;
}
__device__ __forceinline__ void mma16(float* c, uint4 a, unsigned b0, unsigned b1){
  asm volatile(
    "mma.sync.aligned.m16n8k16.row.col.f32.f16.f16.f32 "
    "{%0,%1,%2,%3},{%4,%5,%6,%7},{%8,%9},{%0,%1,%2,%3};"
    : "+f"(c[0]), "+f"(c[1]), "+f"(c[2]), "+f"(c[3])
    : "r"(a.x), "r"(a.y), "r"(a.z), "r"(a.w), "r"(b0), "r"(b1));
}
__device__ __forceinline__ uint4 ldsm4(unsigned addr){
  uint4 r;
  asm volatile("ldmatrix.sync.aligned.m8n8.x4.shared.b16 {%0,%1,%2,%3}, [%4];"
    : "=r"(r.x), "=r"(r.y), "=r"(r.z), "=r"(r.w) : "r"(addr));
  return r;
}
__device__ __forceinline__ uint4 ldsm4t(unsigned addr){
  uint4 r;
  asm volatile("ldmatrix.sync.aligned.m8n8.x4.trans.shared.b16 {%0,%1,%2,%3}, [%4];"
    : "=r"(r.x), "=r"(r.y), "=r"(r.z), "=r"(r.w) : "r"(addr));
  return r;
}
__device__ __forceinline__ void cpa16(unsigned saddr, const void* g){
  asm volatile("cp.async.cg.shared.global [%0], [%1], 16;" :: "r"(saddr), "l"(g) : "memory");
}
#define CP_COMMIT() asm volatile("cp.async.commit_group;" ::: "memory")
#define CP_WAIT(n)  asm volatile("cp.async.wait_group %0;" :: "n"(n) : "memory")

// ============ kernel 0: W f32 -> fp16 ======================================
__global__ void __launch_bounds__(256)
convert_w(const float* __restrict__ W, __half* __restrict__ Wh)
{
  size_t i = ((size_t)blockIdx.x*256 + threadIdx.x)*8;
  float4 v0 = *reinterpret_cast<const float4*>(W+i);
  float4 v1 = *reinterpret_cast<const float4*>(W+i+4);
  uint4 u; u.x=pack2(v0.x,v0.y); u.y=pack2(v0.z,v0.w);
  u.z=pack2(v1.x,v1.y); u.w=pack2(v1.z,v1.w);
  *reinterpret_cast<uint4*>(Wh+i) = u;
}

// ============ kernel 1: K+V compression fused (gathered GEMM) =============
// grid 1024: blocks [0,512) do K, [512,1024) do V.
__global__ void __launch_bounds__(256,2)
compress_kernel(const float* __restrict__ pre_k, const float* __restrict__ kker,
                const float* __restrict__ kbias, __half* __restrict__ outk,
                const float* __restrict__ pre_v, const float* __restrict__ vker,
                const float* __restrict__ vbias, __half* __restrict__ outv)
{
  extern __shared__ char sm[];
  unsigned sbase = (unsigned)__cvta_generic_to_shared(sm);
  int sel = blockIdx.x >> 9;
  int bx  = blockIdx.x & 511;
  const float* pre  = sel ? pre_v : pre_k;
  const float* ker  = sel ? vker  : kker;
  const float* bias = sel ? vbias : kbias;
  __half* outc      = sel ? outv  : outk;

  int tid=threadIdx.x, warp=tid>>5, lane=tid&31, gid=lane>>2, tig=lane&3;
  int bh = bx>>2, t0 = (bx&3)*128;
  int b = bh>>4, h = bh&15;
  const float* base = pre + ((size_t)b*SS*HH + h)*DD;
  int wm = warp>>1, wn = warp&1;

  float acc[2][4][4];
  #pragma unroll
  for (int m=0;m<2;m++)
    #pragma unroll
    for (int j=0;j<4;j++) acc[m][j][0]=acc[m][j][1]=acc[m][j][2]=acc[m][j][3]=0.f;

  auto stage = [&](int w, int bf){
    #pragma unroll
    for (int i=0;i<4;i++){
      int idx = tid + i*256, row = idx>>3, cv = idx&7;
      const float4* g = reinterpret_cast<const float4*>(
          base + (size_t)((t0+row)*4 + w)*(HH*DD) + cv*8);
      float4 v0 = g[0], v1 = g[1];
      uint4 u; u.x=pack2(v0.x,v0.y); u.y=pack2(v0.z,v0.w);
      u.z=pack2(v1.x,v1.y); u.w=pack2(v1.z,v1.w);
      *reinterpret_cast<uint4*>(sm + bf*16384 + row*128 + ((cv ^ (row&7))<<4)) = u;
    }
    #pragma unroll
    for (int i=0;i<2;i++){
      int idx = tid + i*256, row = idx>>3, cv = idx&7;
      const float4* g = reinterpret_cast<const float4*>(
          ker + (size_t)w*DD*DD + row*DD + cv*8);
      float4 v0 = g[0], v1 = g[1];
      uint4 u; u.x=pack2(v0.x,v0.y); u.y=pack2(v0.z,v0.w);
      u.z=pack2(v1.x,v1.y); u.w=pack2(v1.z,v1.w);
      *reinterpret_cast<uint4*>(sm + 32768 + bf*8192 + row*128 + ((cv ^ (row&7))<<4)) = u;
    }
  };

  stage(0,0); __syncthreads();
  for (int w=0; w<4; w++){
    int bf = w&1;
    if (w<3) stage(w+1, bf^1);
    unsigned Ab = sbase + bf*16384;
    unsigned Bb = sbase + 32768 + bf*8192;
    #pragma unroll
    for (int k16=0;k16<4;k16++){
      uint4 aa[2];
      #pragma unroll
      for (int mt=0;mt<2;mt++){
        int row = wm*32 + mt*16 + (lane&7) + ((lane>>3)&1)*8;
        int ch = k16*2 + (lane>>4);
        aa[mt] = ldsm4(Ab + row*128 + (((unsigned)(ch ^ (row&7)))<<4));
      }
      #pragma unroll
      for (int jj=0;jj<2;jj++){
        int row = k16*16 + (lane&7) + ((lane>>4)<<3);
        int ch = wn*4 + jj*2 + ((lane>>3)&1);
        uint4 bb = ldsm4t(Bb + row*128 + (((unsigned)(ch ^ (row&7)))<<4));
        mma16(acc[0][2*jj],   aa[0], bb.x, bb.z);
        mma16(acc[0][2*jj+1], aa[0], bb.y, bb.w);
        mma16(acc[1][2*jj],   aa[1], bb.x, bb.z);
        mma16(acc[1][2*jj+1], aa[1], bb.y, bb.w);
      }
    }
    __syncthreads();
  }

  #pragma unroll
  for (int m=0;m<2;m++){
    int rlo = t0 + wm*32 + m*16 + gid, rhi = rlo+8;
    #pragma unroll
    for (int j=0;j<4;j++){
      int col = wn*32 + j*8 + tig*2;
      float b0 = bias[col], b1 = bias[col+1];
      *reinterpret_cast<__half2*>(outc + ((size_t)bh*SC+rlo)*DD + col) =
          __floats2half2_rn(acc[m][j][0]+b0, acc[m][j][1]+b1);
      *reinterpret_cast<__half2*>(outc + ((size_t)bh*SC+rhi)*DD + col) =
          __floats2half2_rn(acc[m][j][2]+b0, acc[m][j][3]+b1);
    }
  }
}

// ============ kernel 2: flash attention — 16q/warp, 2 CTA/SM (R15) =========
__global__ void __launch_bounds__(256,2)
attn_kernel(const float* __restrict__ preq)
{
  extern __shared__ char sm[];
  unsigned sbase = (unsigned)__cvta_generic_to_shared(sm);
  int tid=threadIdx.x, warp=tid>>5, lane=tid&31, gid=lane>>2, tig=lane&3;
  int bh = blockIdx.y, b = bh>>4, h = bh&15;
  int q0 = blockIdx.x*128, m0 = warp*16;
  const float* qb = preq + ((size_t)b*SS*HH + h)*DD;
  const __half* kb = g_kc + (size_t)bh*SC*DD;
  const __half* vb = g_vc + (size_t)bh*SC*DD;
  const float scale2 = 0.125f * 1.44269504f;

  auto stage = [&](int ch0, int bf){
    int c0 = ch0*64;
    #pragma unroll
    for (int i=0;i<2;i++){
      int idx = tid + i*256, row = idx>>3, cv = idx&7;
      unsigned sw = ((unsigned)(cv ^ (row&7)))<<4;
      cpa16(sbase + bf*8192 + row*128 + sw, kb + (size_t)(c0+row)*DD + cv*8);
      cpa16(sbase + 16384 + bf*8192 + row*128 + sw, vb + (size_t)(c0+row)*DD + cv*8);
    }
  };

  stage(0,0); CP_COMMIT();

  #pragma unroll
  for (int i=0;i<4;i++){
    int idx = tid + i*256, row = idx>>3, cv = idx&7;
    const float4* g = reinterpret_cast<const float4*>(
        qb + (size_t)(q0+row)*(HH*DD) + cv*8);
    float4 v0 = g[0], v1 = g[1];
    uint4 u;
    u.x=pack2(v0.x*scale2, v0.y*scale2); u.y=pack2(v0.z*scale2, v0.w*scale2);
    u.z=pack2(v1.x*scale2, v1.y*scale2); u.w=pack2(v1.z*scale2, v1.w*scale2);
    *reinterpret_cast<uint4*>(sm + 32768 + row*128 + ((cv ^ (row&7))<<4)) = u;
  }
  unsigned Qb = sbase + 32768;
  __syncthreads();

  uint4 qf[4];
  #pragma unroll
  for (int k16=0;k16<4;k16++){
    int row = m0 + (lane&7) + ((lane>>3)&1)*8;
    int cc = k16*2 + (lane>>4);
    qf[k16] = ldsm4(Qb + row*128 + (((unsigned)(cc ^ (row&7)))<<4));
  }

  float o[8][4];
  #pragma unroll
  for (int j=0;j<8;j++) o[j][0]=o[j][1]=o[j][2]=o[j][3]=0.f;
  float accl[4] = {0.f,0.f,0.f,0.f};
  const unsigned bone = (gid==0) ? 0x3C003C00u : 0u;

  for (int ch=0; ch<8; ch++){
    int bf = ch&1;
    CP_WAIT(0);
    __syncthreads();
    if (ch<7){ stage(ch+1, bf^1); CP_COMMIT(); }
    unsigned Kb = sbase + bf*8192;
    unsigned Vb = sbase + 16384 + bf*8192;

    float s[8][4];
    #pragma unroll
    for (int j=0;j<8;j++) s[j][0]=s[j][1]=s[j][2]=s[j][3]=0.f;
    #pragma unroll
    for (int k16=0;k16<4;k16++){
      #pragma unroll
      for (int jj=0;jj<4;jj++){
        int row = jj*16 + (lane&7) + ((lane>>3)&1)*8;
        int cc = k16*2 + (lane>>4);
        uint4 kk = ldsm4(Kb + row*128 + (((unsigned)(cc ^ (row&7)))<<4));
        mma16(s[2*jj],   qf[k16], kk.x, kk.z);
        mma16(s[2*jj+1], qf[k16], kk.y, kk.w);
      }
    }

    uint32_t pa[4][4];
    #pragma unroll
    for (int j=0;j<8;j++){
      unsigned e01 = ex2h2(pack2(s[j][0], s[j][1]));
      unsigned e23 = ex2h2(pack2(s[j][2], s[j][3]));
      int blk = j>>1;
      if ((j&1)==0){ pa[blk][0]=e01; pa[blk][1]=e23; }
      else         { pa[blk][2]=e01; pa[blk][3]=e23; }
    }

    #pragma unroll
    for (int jj=0;jj<4;jj++){
      uint4 a = make_uint4(pa[jj][0], pa[jj][1], pa[jj][2], pa[jj][3]);
      mma16(accl, a, bone, bone);
      #pragma unroll
      for (int dd=0;dd<4;dd++){
        int row = jj*16 + (lane&7) + ((lane>>4)<<3);
        int cc = dd*2 + ((lane>>3)&1);
        uint4 vv = ldsm4t(Vb + row*128 + (((unsigned)(cc ^ (row&7)))<<4));
        mma16(o[2*dd],   a, vv.x, vv.z);
        mma16(o[2*dd+1], a, vv.y, vv.w);
      }
    }
  }

  float rl = __shfl_sync(~0u, accl[0], lane & ~3);
  float rh = __shfl_sync(~0u, accl[2], lane & ~3);
  float il = 1.f/rl, ih = 1.f/rh;
  int qlo = q0+m0+gid, qhi = qlo+8;
  __half* olo = g_ao + ((size_t)(b*SS+qlo)*HH + h)*DD;
  __half* ohi = g_ao + ((size_t)(b*SS+qhi)*HH + h)*DD;
  #pragma unroll
  for (int j=0;j<8;j++){
    int col = j*8 + tig*2;
    *reinterpret_cast<__half2*>(olo + col) =
        __floats2half2_rn(o[j][0]*il, o[j][1]*il);
    *reinterpret_cast<__half2*>(ohi + col) =
        __floats2half2_rn(o[j][2]*ih, o[j][3]*ih);
  }
}

// ============ kernel 3: projection fp16 — R13/R15 config (32x64 warp) ======
// grid (128,8). 8 warps 4m x 2n. k-chunk 64, 3-stage cp.async, 2 CTA/SM.
// smem: A 3x16KB @0, B 3x16KB @49152 -> 98304 B.
__global__ void __launch_bounds__(256,2)
proj_kernel(const __half* __restrict__ Wh, float* __restrict__ out)
{
  extern __shared__ char sm[];
  unsigned sbase = (unsigned)__cvta_generic_to_shared(sm);
  int tid=threadIdx.x, warp=tid>>5, lane=tid&31, gid=lane>>2, tig=lane&3;
  int r0 = blockIdx.x*128, n0 = blockIdx.y*128;
  int wm = warp>>1, wn = warp&1;

  float acc[2][8][4];
  #pragma unroll
  for (int m=0;m<2;m++)
    #pragma unroll
    for (int j=0;j<8;j++) acc[m][j][0]=acc[m][j][1]=acc[m][j][2]=acc[m][j][3]=0.f;

  auto stage = [&](int kc, int st){
    #pragma unroll
    for (int i=0;i<4;i++){
      int idx = tid + i*256, row = idx>>3, cv = idx&7;
      cpa16(sbase + st*16384 + row*128 + (((unsigned)(cv ^ (row&7)))<<4),
            g_ao + (size_t)(r0+row)*DM + kc*64 + cv*8);
    }
    #pragma unroll
    for (int i=0;i<4;i++){
      int idx = tid + i*256, row = idx>>4, cv = idx&15;
      cpa16(sbase + 49152 + st*16384 + row*256 + (((unsigned)(cv ^ (row&7)))<<4),
            Wh + (size_t)(kc*64+row)*DM + n0 + cv*8);
    }
  };

  stage(0,0); CP_COMMIT();
  stage(1,1); CP_COMMIT();

  for (int kc=0; kc<16; kc++){
    int st = kc % 3;
    CP_WAIT(1);
    __syncthreads();
    if (kc+2 < 16){ stage(kc+2, (kc+2)%3); CP_COMMIT(); }
    unsigned Ab = sbase + st*16384;
    unsigned Bb = sbase + 49152 + st*16384;
    #pragma unroll
    for (int k16=0;k16<4;k16++){
      uint4 aa[2];
      #pragma unroll
      for (int mt=0;mt<2;mt++){
        int row = wm*32 + mt*16 + (lane&7) + ((lane>>3)&1)*8;
        int cc = k16*2 + (lane>>4);
        aa[mt] = ldsm4(Ab + row*128 + (((unsigned)(cc ^ (row&7)))<<4));
      }
      #pragma unroll
      for (int dd=0;dd<4;dd++){
        int row = k16*16 + (lane&7) + ((lane>>4)<<3);
        int cc = wn*8 + dd*2 + ((lane>>3)&1);
        uint4 bb = ldsm4t(Bb + row*256 + (((unsigned)(cc ^ (row&7)))<<4));
        mma16(acc[0][2*dd],   aa[0], bb.x, bb.z);
        mma16(acc[0][2*dd+1], aa[0], bb.y, bb.w);
        mma16(acc[1][2*dd],   aa[1], bb.x, bb.z);
        mma16(acc[1][2*dd+1], aa[1], bb.y, bb.w);
      }
    }
  }

  #pragma unroll
  for (int m=0;m<2;m++){
    int rlo = r0 + wm*32 + m*16 + gid, rhi = rlo+8;
    #pragma unroll
    for (int j=0;j<8;j++){
      int col = n0 + wn*64 + j*8 + tig*2;
      *reinterpret_cast<float2*>(out + (size_t)rlo*DM + col) = make_float2(acc[m][j][0], acc[m][j][1]);
      *reinterpret_cast<float2*>(out + (size_t)rhi*DM + col) = make_float2(acc[m][j][2], acc[m][j][3]);
    }
  }
}

extern "C" void kernel_launch(void* const* d_in, const int* in_sizes, int n_in,
                              void* d_out, int out_size)
{
  const float* pre_q = (const float*)d_in[0];
  const float* pre_k = (const float*)d_in[1];
  const float* pre_v = (const float*)d_in[2];
  const float* kker  = (const float*)d_in[3];
  const float* kbias = (const float*)d_in[4];
  const float* vker  = (const float*)d_in[5];
  const float* vbias = (const float*)d_in[6];
  const float* ow    = (const float*)d_in[7];
  float* out = (float*)d_out;

  __half *g_kc_p, *g_vc_p, *g_wh_p;
  cudaGetSymbolAddress((void**)&g_kc_p, g_kc);
  cudaGetSymbolAddress((void**)&g_vc_p, g_vc);
  cudaGetSymbolAddress((void**)&g_wh_p, g_wh);

  const int smemC = 49152;
  const int smemA = 49152;
  const int smemP = 98304;
  cudaFuncSetAttribute(compress_kernel, cudaFuncAttributeMaxDynamicSharedMemorySize, smemC);
  cudaFuncSetAttribute(attn_kernel, cudaFuncAttributeMaxDynamicSharedMemorySize, smemA);
  cudaFuncSetAttribute(proj_kernel, cudaFuncAttributeMaxDynamicSharedMemorySize, smemP);

  convert_w<<<512, 256>>>(ow, g_wh_p);
  compress_kernel<<<1024, 256, smemC>>>(pre_k, kker, kbias, g_kc_p,
                                        pre_v, vker, vbias, g_vc_p);
  attn_kernel<<<dim3(16,128), 256, smemA>>>(pre_q);
  proj_kernel<<<dim3(128,8), 256, smemP>>>(g_wh_p, out);
}